// round 3
// baseline (speedup 1.0000x reference)
#include <cuda_runtime.h>

// ---------------- problem constants ----------------
namespace {
constexpr int BATCH   = 2048;
constexpr int NTIME   = 2048;
constexpr int SEASLEN = 2055;          // 7 + 1 + 2047
constexpr int W       = 288;           // len(arange(0, 2014, 7))
constexpr int CH      = 67;            // 28 (y_in) + 35 (X) + 4 (S)
constexpr int NC      = 12;            // chunks
constexpr int WU      = 441;           // warmup steps = 63 cycles (mult of 7)
constexpr int B1      = 574;           // chunk 0 body length (82*7)
constexpr int CL      = 133;           // chunk i>=1 body length (19*7), last=143
constexpr long long INS_ELEMS  = (long long)W * BATCH * CH;  // 39,518,208
constexpr long long OUTS_ELEMS = (long long)W * BATCH * 7;   //  4,128,768
constexpr long long LEV_ELEMS  = (long long)BATCH * NTIME;   //  4,194,304
}

// chunk owning the write at time t (levels[t], g_L[t]; seasonal[j] -> t=j-7)
__device__ __forceinline__ int chunk_of(int t) {
    return (t <= B1) ? 0 : min(NC - 1, 1 + (t - (B1 + 1)) / CL);
}
__device__ __forceinline__ int body_start(int ci) {   // ci >= 1
    return B1 + (ci - 1) * CL;
}

// scratch (no runtime allocation allowed)
__device__ float g_L[BATCH * NTIME];    // raw log(Y[b,t]/seasonal_raw[b,t])
__device__ float g_LL[W * BATCH];       // raw log(levels_raw[b, 7w+27]), [w][b]
__device__ float g_anchor[NC * BATCH];  // chunk i's raw lev at t = B_i
__device__ float g_gamma[NC * BATCH];   // true = raw * gamma
__device__ float g_lgam[NC * BATCH];    // log(gamma)

// ---------------- kernel 1: chunked speculative ES scan ---------------------
// grid (BATCH/128, NC). Chunk 0 exact from t=0; chunks i>=1 warm up WU steps
// (converging onto the true trajectory up to the exact scale symmetry
// (lev,s)->(lev/g, g*s)), then write their body. Scale fixed later.
__global__ void es_scan(const float* __restrict__ Y,
                        const int*   __restrict__ idxs,
                        const float* __restrict__ emb,
                        float* __restrict__ levels,     // [B][2048]  (raw)
                        float* __restrict__ seasonal)   // [B][2055]  (raw)
{
    int b  = blockIdx.x * blockDim.x + threadIdx.x;
    int ci = blockIdx.y;

    const float* e = emb + (long long)idxs[b] * 9;
    float a   = 1.f / (1.f + __expf(-e[0]));   // lev_sms
    float bs  = 1.f / (1.f + __expf(-e[1]));   // seas_sms
    float am  = 1.f - a;
    float bsm = 1.f - bs;

    const float* Yr  = Y        + (long long)b * NTIME;
    float* levr      = levels   + (long long)b * NTIME;
    float* sear      = seasonal + (long long)b * SEASLEN;
    float* Lr        = g_L      + (long long)b * NTIME;

    float buf[7];
    float lev;
    int   k, body;

    if (ci == 0) {
        float is0 = __expf(e[2]);
#pragma unroll
        for (int j = 0; j < 6; j++) buf[j] = __expf(e[3 + j]);
        buf[6] = is0;
        sear[0] = is0;
#pragma unroll
        for (int j = 0; j < 6; j++) sear[1 + j] = buf[j];
        sear[7] = is0;
        lev = __fdividef(Yr[0], is0);
        levr[0] = lev;
        Lr[0]   = __logf(lev);
        k = 0;
        body = B1;                           // 574 steps
    } else {
        int bstart = body_start(ci);
        k = bstart - WU;                     // multiple of 7 -> phase 0
        lev = Yr[k];
#pragma unroll
        for (int j = 0; j < 7; j++) buf[j] = 1.0f;
        for (int g = 0; g < WU / 7; g++) {   // warmup: no writes
#pragma unroll
            for (int sl = 0; sl < 7; sl++) {
                float y  = Yr[k + 1];
                float s  = buf[sl];
                float q  = __fdividef(y, s);
                float nl = fmaf(a, q, am * lev);
                float ns = fmaf(bs, __fdividef(y, nl), bsm * s);
                buf[sl] = ns;
                lev     = nl;
                k++;
            }
        }
        g_anchor[ci * BATCH + b] = lev;      // raw lev at t = bstart
        body = (ci == NC - 1) ? (NTIME - 1 - bstart) : CL;   // 133 or 143
    }

    int nfull = body / 7;
    int tail  = body % 7;                    // 0 except last chunk (143%7=3)

    for (int g = 0; g < nfull; g++) {
#pragma unroll
        for (int sl = 0; sl < 7; sl++) {
            float y  = Yr[k + 1];
            float s  = buf[sl];
            float q  = __fdividef(y, s);
            float nl = fmaf(a, q, am * lev);
            float ns = fmaf(bs, __fdividef(y, nl), bsm * s);
            buf[sl] = ns;
            lev     = nl;
            levr[k + 1] = nl;
            sear[8 + k] = ns;
            Lr[k + 1]   = __logf(q);          // s here == seasonal_raw[k+1]
            if (sl == 5 && (unsigned)(k - 26) <= 2009u)    // k = 7w+26
                g_LL[((k - 26) / 7) * BATCH + b] = __logf(nl);
            k++;
        }
    }
#pragma unroll
    for (int sl = 0; sl < 6; sl++) {
        if (sl < tail) {
            float y  = Yr[k + 1];
            float s  = buf[sl];
            float q  = __fdividef(y, s);
            float nl = fmaf(a, q, am * lev);
            float ns = fmaf(bs, __fdividef(y, nl), bsm * s);
            buf[sl] = ns;
            lev     = nl;
            levr[k + 1] = nl;
            sear[8 + k] = ns;
            Lr[k + 1]   = __logf(q);
            if (sl == 5 && (unsigned)(k - 26) <= 2009u)
                g_LL[((k - 26) / 7) * BATCH + b] = __logf(nl);
            k++;
        }
    }
}

// ---------------- kernel 2: sequential per-row scale combine ----------------
__global__ void combine_gamma(const float* __restrict__ levels)
{
    int b = blockIdx.x * blockDim.x + threadIdx.x;
    if (b >= BATCH) return;
    float g = 1.0f;
    g_gamma[b] = 1.0f;
    g_lgam[b]  = 0.0f;
    for (int i = 1; i < NC; i++) {
        int   Bi   = body_start(i);
        float prev = levels[(long long)b * NTIME + Bi];  // raw, chunk i-1
        float anc  = g_anchor[i * BATCH + b];            // raw, chunk i
        g = g * __fdividef(prev, anc);
        g_gamma[i * BATCH + b] = g;
        g_lgam[i * BATCH + b]  = __logf(g);
    }
}

// ---------------- kernel 3: rescale levels & seasonal (outputs) -------------
__global__ void fixup(float* __restrict__ levels, float* __restrict__ seasonal)
{
    int idx = blockIdx.x * blockDim.x + threadIdx.x;
    if (idx < (int)LEV_ELEMS) {
        int t = idx & (NTIME - 1);
        int b = idx >> 11;
        levels[idx] *= g_gamma[chunk_of(t) * BATCH + b];
    } else {
        int j2 = idx - (int)LEV_ELEMS;
        if (j2 >= BATCH * SEASLEN) return;
        int b = j2 / SEASLEN;
        int j = j2 % SEASLEN;
        if (j >= 8) {
            int ch = chunk_of(j - 7);        // seasonal[8+k] written at t=k+1
            seasonal[j2] = __fdividef(seasonal[j2], g_gamma[ch * BATCH + b]);
        }
    }
}

// ---------------- kernel 4: insample windows (W, B, 67) ---------------------
__global__ void win_insample(const float* __restrict__ X,
                             const float* __restrict__ S,
                             float* __restrict__ out)
{
    int idx = blockIdx.x * blockDim.x + threadIdx.x;   // < 39,518,208
    int c  = idx % CH;
    int bw = idx / CH;
    int b  = bw & (BATCH - 1);
    int w  = bw >> 11;
    int ws = w * 7;
    float v;
    if (c < 28) {
        int t   = ws + c;
        int ch1 = chunk_of(t);                // chunk of L[t]
        int ch2 = chunk_of(ws + 27);          // chunk of lev at t=7w+27
        v = (g_L[b * NTIME + t] + g_lgam[ch1 * BATCH + b])
          - (g_LL[w * BATCH + b] + g_lgam[ch2 * BATCH + b]);
    } else if (c < 63) {
        v = X[b * NTIME + ws + (c - 28)];     // N_T == 1
    } else {
        v = S[(b << 2) + (c - 63)];
    }
    out[idx] = v;
}

// ---------------- kernel 5: outsample windows (W, B, 7) ---------------------
__global__ void win_outsample(const float* __restrict__ Y,
                              float* __restrict__ out)
{
    int idx = blockIdx.x * blockDim.x + threadIdx.x;   // < 4,128,768
    int j  = idx % 7;
    int bw = idx / 7;
    int b  = bw & (BATCH - 1);
    int w  = bw >> 11;
    out[idx] = Y[b * NTIME + w * 7 + 28 + j];
}

// ---------------- launch -----------------------------------------------------
extern "C" void kernel_launch(void* const* d_in, const int* in_sizes, int n_in,
                              void* d_out, int out_size)
{
    const float* S    = (const float*)d_in[0];   // (2048, 4)
    const float* Y    = (const float*)d_in[1];   // (2048, 2048)
    const float* X    = (const float*)d_in[2];   // (2048, 1, 2048)
    const int*   idxs = (const int*)  d_in[3];   // (2048,)
    const float* emb  = (const float*)d_in[4];   // (100000, 9)

    float* out      = (float*)d_out;
    float* ins      = out;                                      // 39,518,208
    float* outs     = out + INS_ELEMS;                          //  4,128,768
    float* levels   = out + INS_ELEMS + OUTS_ELEMS;             //  4,194,304
    float* seasonal = out + INS_ELEMS + OUTS_ELEMS + LEV_ELEMS; // 2048*2055

    es_scan<<<dim3(BATCH / 128, NC), 128>>>(Y, idxs, emb, levels, seasonal);
    combine_gamma<<<BATCH / 256, 256>>>(levels);

    int fix_n = (int)LEV_ELEMS + BATCH * SEASLEN;               // 8,402,944
    fixup<<<(fix_n + 255) / 256, 256>>>(levels, seasonal);

    win_insample<<<(int)(INS_ELEMS / 256), 256>>>(X, S, ins);   // exact multiple
    win_outsample<<<(int)(OUTS_ELEMS / 256), 256>>>(Y, outs);   // exact multiple
}

// round 4
// speedup vs baseline: 1.5468x; 1.5468x over previous
#include <cuda_runtime.h>

// ---------------- problem constants ----------------
namespace {
constexpr int BATCH   = 2048;
constexpr int NTIME   = 2048;
constexpr int SEASLEN = 2055;          // 7 + 1 + 2047
constexpr int W       = 288;           // len(arange(0, 2014, 7))
constexpr int CH      = 67;            // 28 (y_in) + 35 (X) + 4 (S)
constexpr int NC      = 16;            // chunks
constexpr int WU      = 441;           // warmup steps = 63 cycles (mult of 7)
constexpr int B1      = 574;           // chunk 0 body length (82*7)
constexpr int CL      = 98;            // chunk i>=1 body (14*7), last = 101
constexpr long long INS_ELEMS  = (long long)W * BATCH * CH;  // 39,518,208
constexpr long long OUTS_ELEMS = (long long)W * BATCH * 7;   //  4,128,768
constexpr long long LEV_ELEMS  = (long long)BATCH * NTIME;   //  4,194,304
}

__device__ __forceinline__ int chunk_of(int t) {      // writer of levels[t]
    return (t <= B1) ? 0 : min(NC - 1, 1 + (t - (B1 + 1)) / CL);
}
__device__ __forceinline__ int body_start(int ci) {   // ci >= 1
    return B1 + (ci - 1) * CL;
}

// ---------------- scratch (time-major: [t][b]) ------------------------------
__device__ float g_Yt [NTIME * BATCH];
__device__ float g_Xt [NTIME * BATCH];
__device__ float g_levT[NTIME * BATCH];   // raw levels, [t][b]
__device__ float g_seaT[SEASLEN * BATCH]; // raw seasonal, [j][b]
__device__ float g_LT [NTIME * BATCH];    // raw log(Y/seas), [t][b]
__device__ float g_LL [W * BATCH];        // log(lev) at t=7w+27, [w][b]
__device__ float g_St [4 * BATCH];        // S transposed
__device__ float g_anchor[NC * BATCH];
__device__ float g_gamma [NC * BATCH];    // true = raw * gamma
__device__ float g_lgam  [NC * BATCH];
__device__ float g_rgam  [NC * BATCH];    // 1/gamma

// ---------------- tiled 2048x2048 transpose ([b][t] -> [t][b]) --------------
__global__ void transpose2048(const float* __restrict__ src, float* __restrict__ dst)
{
    __shared__ float tile[32][33];
    int x  = blockIdx.x * 32 + threadIdx.x;   // t
    int y0 = blockIdx.y * 32;                 // b
#pragma unroll
    for (int j = threadIdx.y; j < 32; j += 8)
        tile[j][threadIdx.x] = src[(y0 + j) * NTIME + x];
    __syncthreads();
    int x2 = blockIdx.y * 32 + threadIdx.x;   // b
    int y2 = blockIdx.x * 32;                 // t
#pragma unroll
    for (int j = threadIdx.y; j < 32; j += 8)
        dst[(y2 + j) * BATCH + x2] = tile[threadIdx.x][j];
}

// ---------------- kernel 1: chunked speculative ES scan (coalesced) ---------
__global__ void es_scan(const int*   __restrict__ idxs,
                        const float* __restrict__ emb)
{
    int b  = blockIdx.x * blockDim.x + threadIdx.x;
    int ci = blockIdx.y;

    const float* e = emb + (long long)idxs[b] * 9;
    float a   = 1.f / (1.f + __expf(-e[0]));
    float bs  = 1.f / (1.f + __expf(-e[1]));
    float am  = 1.f - a;
    float bsm = 1.f - bs;

    const float* yp = g_Yt  + b;
    float*       lvp= g_levT+ b;
    float*       sep= g_seaT+ b;
    float*       lp = g_LT  + b;

    float buf[7];
    float lev;
    int   k, body;

    if (ci == 0) {
        float is0 = __expf(e[2]);
#pragma unroll
        for (int j = 0; j < 6; j++) buf[j] = __expf(e[3 + j]);
        buf[6] = is0;
        sep[0] = is0;
#pragma unroll
        for (int j = 0; j < 6; j++) sep[(1 + j) << 11] = buf[j];
        sep[7 << 11] = is0;
        lev = __fdividef(yp[0], is0);
        lvp[0] = lev;
        lp[0]  = __logf(lev);
        k = 0;
        body = B1;
    } else {
        int bstart = body_start(ci);
        k = bstart - WU;                     // multiple of 7 -> phase 0
        lev = yp[k << 11];
#pragma unroll
        for (int j = 0; j < 7; j++) buf[j] = 1.0f;
        for (int g = 0; g < WU / 7; g++) {   // warmup: no writes
#pragma unroll
            for (int sl = 0; sl < 7; sl++) {
                float y  = yp[(k + 1) << 11];
                float s  = buf[sl];
                float q  = __fdividef(y, s);
                float nl = fmaf(a, q, am * lev);
                float ns = fmaf(bs, __fdividef(y, nl), bsm * s);
                buf[sl] = ns;
                lev     = nl;
                k++;
            }
        }
        g_anchor[ci * BATCH + b] = lev;
        body = (ci == NC - 1) ? (NTIME - 1 - bstart) : CL;
    }

    int nfull = body / 7;
    int tail  = body % 7;

    for (int g = 0; g < nfull; g++) {
#pragma unroll
        for (int sl = 0; sl < 7; sl++) {
            float y  = yp[(k + 1) << 11];
            float s  = buf[sl];
            float q  = __fdividef(y, s);
            float nl = fmaf(a, q, am * lev);
            float ns = fmaf(bs, __fdividef(y, nl), bsm * s);
            buf[sl] = ns;
            lev     = nl;
            lvp[(k + 1) << 11] = nl;
            sep[(8 + k) << 11] = ns;
            lp [(k + 1) << 11] = __logf(q);   // s == seasonal_raw[k+1]
            if (sl == 5 && (unsigned)(k - 26) <= 2009u)     // k = 7w+26
                g_LL[((k - 26) / 7) * BATCH + b] = __logf(nl);
            k++;
        }
    }
#pragma unroll
    for (int sl = 0; sl < 6; sl++) {
        if (sl < tail) {
            float y  = yp[(k + 1) << 11];
            float s  = buf[sl];
            float q  = __fdividef(y, s);
            float nl = fmaf(a, q, am * lev);
            float ns = fmaf(bs, __fdividef(y, nl), bsm * s);
            buf[sl] = ns;
            lev     = nl;
            lvp[(k + 1) << 11] = nl;
            sep[(8 + k) << 11] = ns;
            lp [(k + 1) << 11] = __logf(q);
            if (sl == 5 && (unsigned)(k - 26) <= 2009u)
                g_LL[((k - 26) / 7) * BATCH + b] = __logf(nl);
            k++;
        }
    }
}

// ---------------- kernel 2: per-row scale combine (+ S transpose) -----------
__global__ void combine_gamma(const float* __restrict__ S)
{
    int b = blockIdx.x * blockDim.x + threadIdx.x;
    if (b >= BATCH) return;
    float g = 1.0f;
    g_gamma[b] = 1.0f; g_lgam[b] = 0.0f; g_rgam[b] = 1.0f;
    for (int i = 1; i < NC; i++) {
        int   Bi   = body_start(i);
        float prev = g_levT[Bi * BATCH + b];     // raw, chunk i-1 (coalesced)
        float anc  = g_anchor[i * BATCH + b];    // raw, chunk i
        g = g * __fdividef(prev, anc);
        g_gamma[i * BATCH + b] = g;
        g_lgam [i * BATCH + b] = __logf(g);
        g_rgam [i * BATCH + b] = __fdividef(1.0f, g);
    }
#pragma unroll
    for (int j = 0; j < 4; j++) g_St[j * BATCH + b] = S[b * 4 + j];
}

// ---------------- kernel 3a: levels = transpose(g_levT) * gamma -------------
__global__ void fix_levels(float* __restrict__ out)
{
    __shared__ float tile[32][33];
    int t0 = blockIdx.x * 32;
    int b0 = blockIdx.y * 32;
#pragma unroll
    for (int j = threadIdx.y; j < 32; j += 8)
        tile[j][threadIdx.x] = g_levT[(t0 + j) * BATCH + b0 + threadIdx.x];
    __syncthreads();
    int t = t0 + threadIdx.x;
    int ch = chunk_of(t);
#pragma unroll
    for (int j = threadIdx.y; j < 32; j += 8) {
        int b = b0 + j;
        out[b * NTIME + t] = tile[threadIdx.x][j] * g_gamma[ch * BATCH + b];
    }
}

// ---------------- kernel 3b: seasonal = transpose(g_seaT) / gamma -----------
__global__ void fix_seasonal(float* __restrict__ out)
{
    __shared__ float tile[32][33];
    int t0 = blockIdx.x * 32;        // column j of seasonal (0..2054)
    int b0 = blockIdx.y * 32;
#pragma unroll
    for (int j = threadIdx.y; j < 32; j += 8) {
        int jj = t0 + j;
        if (jj < SEASLEN)
            tile[j][threadIdx.x] = g_seaT[jj * BATCH + b0 + threadIdx.x];
    }
    __syncthreads();
    int jj = t0 + threadIdx.x;
    if (jj >= SEASLEN) return;
    float scale_needed = (jj >= 8);
    int ch = (jj >= 8) ? chunk_of(jj - 7) : 0;   // seasonal[8+k] written at t=k+1
#pragma unroll
    for (int j = threadIdx.y; j < 32; j += 8) {
        int b = b0 + j;
        float v = tile[threadIdx.x][j];
        if (scale_needed) v *= g_rgam[ch * BATCH + b];
        out[b * SEASLEN + jj] = v;
    }
}

// ---------------- kernel 3c: fold lgam into g_LL -----------------------------
__global__ void fix_LL()
{
    int idx = blockIdx.x * blockDim.x + threadIdx.x;   // < W*BATCH
    int w = idx >> 11;
    int b = idx & (BATCH - 1);
    g_LL[idx] += g_lgam[chunk_of(w * 7 + 27) * BATCH + b];
}

// ---------------- kernel 4: insample windows (smem-staged) -------------------
// Block = 256 threads, covers 32 consecutive (w,b) pairs (same w: 2048%32==0).
// Phase 1: warp 'wi' handles channels c = wi, wi+8, ...; lanes span b (coalesced
// reads from time-major scratch). Phase 2: coalesced linear write of 32*67 floats.
__global__ void win_insample(float* __restrict__ out)
{
    __shared__ float tile[32 * 69];
    int bw0  = blockIdx.x * 32;
    int w    = bw0 >> 11;
    int ws   = w * 7;
    int lane = threadIdx.x & 31;
    int warp = threadIdx.x >> 5;
    int b    = (bw0 & (BATCH - 1)) + lane;

    // per-(w,b) constant: true log-level at t = ws+27 (lgam already folded in)
    float LLc = g_LL[w * BATCH + b];

    for (int c = warp; c < CH; c += 8) {
        float v;
        if (c < 28) {
            int t = ws + c;
            v = g_LT[t * BATCH + b] + g_lgam[chunk_of(t) * BATCH + b] - LLc;
        } else if (c < 63) {
            v = g_Xt[(ws + c - 28) * BATCH + b];
        } else {
            v = g_St[(c - 63) * BATCH + b];
        }
        tile[lane * 69 + c] = v;
    }
    __syncthreads();

    long long base = (long long)bw0 * CH;
#pragma unroll 4
    for (int i = threadIdx.x; i < 32 * CH; i += 256) {
        int g = i / CH;
        int c = i - g * CH;
        out[base + i] = tile[g * 69 + c];
    }
}

// ---------------- kernel 5: outsample windows (W, B, 7) ---------------------
__global__ void win_outsample(const float* __restrict__ Y,
                              float* __restrict__ out)
{
    int idx = blockIdx.x * blockDim.x + threadIdx.x;   // < 4,128,768
    int j  = idx % 7;
    int bw = idx / 7;
    int b  = bw & (BATCH - 1);
    int w  = bw >> 11;
    out[idx] = Y[b * NTIME + w * 7 + 28 + j];
}

// ---------------- launch -----------------------------------------------------
extern "C" void kernel_launch(void* const* d_in, const int* in_sizes, int n_in,
                              void* d_out, int out_size)
{
    const float* S    = (const float*)d_in[0];   // (2048, 4)
    const float* Y    = (const float*)d_in[1];   // (2048, 2048)
    const float* X    = (const float*)d_in[2];   // (2048, 1, 2048)
    const int*   idxs = (const int*)  d_in[3];   // (2048,)
    const float* emb  = (const float*)d_in[4];   // (100000, 9)

    float* out      = (float*)d_out;
    float* ins      = out;                                      // 39,518,208
    float* outs     = out + INS_ELEMS;                          //  4,128,768
    float* levels   = out + INS_ELEMS + OUTS_ELEMS;             //  4,194,304
    float* seasonal = out + INS_ELEMS + OUTS_ELEMS + LEV_ELEMS; // 2048*2055

    float* yt; cudaGetSymbolAddress((void**)&yt, g_Yt);
    float* xt; cudaGetSymbolAddress((void**)&xt, g_Xt);

    dim3 tb(32, 8);
    transpose2048<<<dim3(64, 64), tb>>>(Y, yt);
    transpose2048<<<dim3(64, 64), tb>>>(X, xt);

    es_scan<<<dim3(BATCH / 128, NC), 128>>>(idxs, emb);
    combine_gamma<<<BATCH / 256, 256>>>(S);

    fix_levels  <<<dim3(64, 64), tb>>>(levels);
    fix_seasonal<<<dim3(65, 64), tb>>>(seasonal);
    fix_LL      <<<(W * BATCH) / 256, 256>>>();

    win_insample <<<W * BATCH / 32, 256>>>(ins);
    win_outsample<<<(int)(OUTS_ELEMS / 256), 256>>>(Y, outs);
}